// round 3
// baseline (speedup 1.0000x reference)
#include <cuda_runtime.h>
#include <cuda_bf16.h>

#define MAX_N 100000
#define N_GRAPHS 64
#define FEAT 64
#define MAX_E 1600000

// ---------------- scratch (device globals; no allocations) ----------------
__device__ float g_S[MAX_N * FEAT];       // aggregated (mean) neighbor features
__device__ float g_h[MAX_N * FEAT];       // layer output (reused in-place)
__device__ int   g_deg[MAX_N];            // in-degree histogram
__device__ int   g_rowstart[MAX_N + 1];   // CSR row starts
__device__ int   g_cursor[MAX_N];         // placement cursors
__device__ int   g_srcs[MAX_E];           // CSR: src per edge, bucketed by dst
__device__ int   g_bsum[128];
__device__ int   g_boff[128];
__device__ float g_pooled[N_GRAPHS * FEAT];
__device__ int   g_ei64;
__device__ int   g_b64;

// ---------------- dtype detection (int32 vs int64 indices) ----------------
__global__ void detect_kernel(const void* ei, const void* batch, int nE, int nN) {
    if (threadIdx.x == 0 && blockIdx.x == 0) {
        int e64 = 1;
        const long long* p = (const long long*)ei;
        for (int i = 0; i < 64 && i < nE; i++) {
            long long v = p[i];
            if (v < 0 || v >= (long long)nN) { e64 = 0; break; }
        }
        g_ei64 = e64;
        int b64 = 1;
        const long long* q = (const long long*)batch;
        for (int i = 0; i < 8; i++) {
            int idx = nN / 2 - 1 - i;
            if (idx < 0) break;
            long long v = q[idx];
            if (v < 0 || v >= 64) { b64 = 0; break; }
        }
        g_b64 = b64;
    }
}

// ---------------- CSR build ----------------
__global__ void zero_deg_kernel(int nN) {
    int i = blockIdx.x * blockDim.x + threadIdx.x;
    if (i < nN) g_deg[i] = 0;
}

__global__ void hist_kernel(const void* __restrict__ ei_v, int nE) {
    int e = blockIdx.x * blockDim.x + threadIdx.x;
    if (e >= nE) return;
    int dst;
    if (g_ei64) dst = (int)((const long long*)ei_v)[(long long)nE + e];
    else        dst = ((const int*)ei_v)[nE + e];
    atomicAdd(&g_deg[dst], 1);
}

__global__ void scan_block_kernel(int nN) {
    __shared__ int wsum[8];
    __shared__ int woff[8];
    int blk = blockIdx.x, t = threadIdx.x;
    int base = blk * 1024 + t * 4;
    int v0 = (base + 0 < nN) ? g_deg[base + 0] : 0;
    int v1 = (base + 1 < nN) ? g_deg[base + 1] : 0;
    int v2 = (base + 2 < nN) ? g_deg[base + 2] : 0;
    int v3 = (base + 3 < nN) ? g_deg[base + 3] : 0;
    int i0 = v0, i1 = i0 + v1, i2 = i1 + v2, i3 = i2 + v3;
    int tot = i3;
    int lane = t & 31, w = t >> 5;
    int sc = tot;
    #pragma unroll
    for (int off = 1; off < 32; off <<= 1) {
        int n = __shfl_up_sync(0xffffffffu, sc, off);
        if (lane >= off) sc += n;
    }
    if (lane == 31) wsum[w] = sc;
    __syncthreads();
    if (t < 8) {
        int v = wsum[t];
        int s = v;
        #pragma unroll
        for (int off = 1; off < 8; off <<= 1) {
            int n = __shfl_up_sync(0xffu, s, off);
            if (t >= off) s += n;
        }
        woff[t] = s - v;
        if (t == 7) g_bsum[blk] = s;
    }
    __syncthreads();
    int excl = woff[w] + (sc - tot);
    if (base + 0 < nN) g_rowstart[base + 0] = excl;
    if (base + 1 < nN) g_rowstart[base + 1] = excl + i0;
    if (base + 2 < nN) g_rowstart[base + 2] = excl + i1;
    if (base + 3 < nN) g_rowstart[base + 3] = excl + i2;
}

__global__ void scan_tops_kernel(int nBlocks) {
    __shared__ int wsum[4];
    __shared__ int woff[4];
    int t = threadIdx.x;
    int v = (t < nBlocks) ? g_bsum[t] : 0;
    int lane = t & 31, w = t >> 5;
    int s = v;
    #pragma unroll
    for (int off = 1; off < 32; off <<= 1) {
        int n = __shfl_up_sync(0xffffffffu, s, off);
        if (lane >= off) s += n;
    }
    if (lane == 31) wsum[w] = s;
    __syncthreads();
    if (t < 4) {
        int vv = wsum[t];
        int ss = vv;
        #pragma unroll
        for (int off = 1; off < 4; off <<= 1) {
            int n = __shfl_up_sync(0xfu, ss, off);
            if (t >= off) ss += n;
        }
        woff[t] = ss - vv;
    }
    __syncthreads();
    if (t < nBlocks) g_boff[t] = (s - v) + woff[w];
}

__global__ void scan_add_kernel(int nN, int nE) {
    int i = blockIdx.x * blockDim.x + threadIdx.x;
    if (i < nN) {
        int s = g_rowstart[i] + g_boff[i >> 10];
        g_rowstart[i] = s;
        g_cursor[i] = s;
    }
    if (i == 0) g_rowstart[nN] = nE;
}

__global__ void fill_kernel(const void* __restrict__ ei_v, int nE) {
    int e = blockIdx.x * blockDim.x + threadIdx.x;
    if (e >= nE) return;
    int src, dst;
    if (g_ei64) {
        const long long* ei = (const long long*)ei_v;
        src = (int)ei[e];
        dst = (int)ei[(long long)nE + e];
    } else {
        const int* ei = (const int*)ei_v;
        src = ei[e];
        dst = ei[nE + e];
    }
    int pos = atomicAdd(&g_cursor[dst], 1);
    g_srcs[pos] = src;
}

// ---------------- gather-mean: one warp per node -----------------------
// 32 lanes x float2 = 256B per neighbor row; no intra-warp divergence.
__global__ void gather_kernel(const float* __restrict__ x, int nN, int fromH) {
    int gtid = blockIdx.x * blockDim.x + threadIdx.x;
    int node = gtid >> 5;
    int lane = gtid & 31;
    if (node >= nN) return;
    const float* base = fromH ? (const float*)g_h : x;
    int s = g_rowstart[node];
    int e = g_rowstart[node + 1];
    float ax = 0.f, ay = 0.f;
    int i = s;
    for (; i + 4 <= e; i += 4) {
        int s0 = __ldg(&g_srcs[i]);
        int s1 = __ldg(&g_srcs[i + 1]);
        int s2 = __ldg(&g_srcs[i + 2]);
        int s3 = __ldg(&g_srcs[i + 3]);
        float2 v0 = __ldg((const float2*)(base + (size_t)s0 * FEAT) + lane);
        float2 v1 = __ldg((const float2*)(base + (size_t)s1 * FEAT) + lane);
        float2 v2 = __ldg((const float2*)(base + (size_t)s2 * FEAT) + lane);
        float2 v3 = __ldg((const float2*)(base + (size_t)s3 * FEAT) + lane);
        ax += (v0.x + v1.x) + (v2.x + v3.x);
        ay += (v0.y + v1.y) + (v2.y + v3.y);
    }
    for (; i < e; i++) {
        int s0 = __ldg(&g_srcs[i]);
        float2 v0 = __ldg((const float2*)(base + (size_t)s0 * FEAT) + lane);
        ax += v0.x; ay += v0.y;
    }
    float inv = 1.0f / fmaxf((float)(e - s), 1.0f);
    float2 o = make_float2(ax * inv, ay * inv);
    reinterpret_cast<float2*>(g_S)[node * 32 + lane] = o;
}

// ---------------- fused RGCN layer GEMM with packed f32x2 FMA ------------
// out[i,:] = relu( S[i,:] @ Wrel + X[i,:] @ Wroot + b ), K=128 fused.
// f32x2 lanes = (even-k partial, odd-k partial); A pairs come from row-major
// input LDS.128, B pairs from k-transposed weight tile. Zero duplication MOVs.
__global__ void rgcn_gemm(const float* __restrict__ Xin,
                          const float* __restrict__ Wrel,
                          const float* __restrict__ Wroot,
                          const float* __restrict__ bias,
                          int nRows, int xIsH) {
    const float* X = xIsH ? (const float*)g_h : Xin;
    __shared__ float4 sIn[64][33];     // [row][k4], padded
    __shared__ float  sWt[64][132];    // [col][k] transposed weights, padded
    __shared__ float  sB[64];

    int tid = threadIdx.x;
    int rowBase = blockIdx.x * 64;

    // weights: global row-major [k][64] -> smem transposed [col][k]
    #pragma unroll
    for (int i = tid; i < 2048; i += 256) {
        int k = i >> 4, j = i & 15;
        float4 w = (k < 64) ? reinterpret_cast<const float4*>(Wrel)[k * 16 + j]
                            : reinterpret_cast<const float4*>(Wroot)[(k - 64) * 16 + j];
        sWt[4 * j + 0][k] = w.x;
        sWt[4 * j + 1][k] = w.y;
        sWt[4 * j + 2][k] = w.z;
        sWt[4 * j + 3][k] = w.w;
    }
    if (tid < 64) sB[tid] = bias[tid];

    // input tile: K = [S row | X row]
    #pragma unroll
    for (int i = tid; i < 2048; i += 256) {
        int r = i >> 5, q = i & 31;
        int row = rowBase + r;
        float4 v = make_float4(0.f, 0.f, 0.f, 0.f);
        if (row < nRows) {
            if (q < 16) v = reinterpret_cast<const float4*>(g_S)[row * 16 + q];
            else        v = reinterpret_cast<const float4*>(X)[row * 16 + (q - 16)];
        }
        sIn[r][q] = v;
    }
    __syncthreads();

    int tx = tid & 15;   // cols 4tx..4tx+3
    int ty = tid >> 4;   // rows ty + 16*i
    unsigned long long acc[4][4];
    #pragma unroll
    for (int i = 0; i < 4; i++)
        #pragma unroll
        for (int j = 0; j < 4; j++) acc[i][j] = 0ull;

    #pragma unroll 4
    for (int k4 = 0; k4 < 32; ++k4) {
        ulonglong2 a[4];
        #pragma unroll
        for (int i = 0; i < 4; i++)
            a[i] = *reinterpret_cast<const ulonglong2*>(&sIn[ty + 16 * i][k4]);
        ulonglong2 w[4];
        #pragma unroll
        for (int j = 0; j < 4; j++)
            w[j] = *reinterpret_cast<const ulonglong2*>(&sWt[4 * tx + j][k4 * 4]);
        #pragma unroll
        for (int i = 0; i < 4; i++) {
            #pragma unroll
            for (int j = 0; j < 4; j++) {
                asm("fma.rn.f32x2 %0, %1, %2, %0;"
                    : "+l"(acc[i][j]) : "l"(a[i].x), "l"(w[j].x));
                asm("fma.rn.f32x2 %0, %1, %2, %0;"
                    : "+l"(acc[i][j]) : "l"(a[i].y), "l"(w[j].y));
            }
        }
    }

    #pragma unroll
    for (int i = 0; i < 4; i++) {
        int row = rowBase + ty + 16 * i;
        if (row < nRows) {
            float res[4];
            #pragma unroll
            for (int j = 0; j < 4; j++) {
                unsigned int lo, hi;
                asm("mov.b64 {%0, %1}, %2;" : "=r"(lo), "=r"(hi) : "l"(acc[i][j]));
                res[j] = __uint_as_float(lo) + __uint_as_float(hi);
            }
            float4 o;
            o.x = fmaxf(res[0] + sB[tx * 4 + 0], 0.f);
            o.y = fmaxf(res[1] + sB[tx * 4 + 1], 0.f);
            o.z = fmaxf(res[2] + sB[tx * 4 + 2], 0.f);
            o.w = fmaxf(res[3] + sB[tx * 4 + 3], 0.f);
            reinterpret_cast<float4*>(g_h)[row * 16 + tx] = o;
        }
    }
}

// ---------------- global mean pool ----------------
__device__ __forceinline__ long long batch_at(const void* b, int i, int is64) {
    return is64 ? ((const long long*)b)[i] : (long long)((const int*)b)[i];
}

__global__ void pool_kernel(const void* __restrict__ batch, int nRows) {
    int g = blockIdx.x;
    int is64 = g_b64;
    int lo = 0, hi = nRows;
    while (lo < hi) { int m = (lo + hi) >> 1; if (batch_at(batch, m, is64) < g) lo = m + 1; else hi = m; }
    int start = lo;
    lo = 0; hi = nRows;
    while (lo < hi) { int m = (lo + hi) >> 1; if (batch_at(batch, m, is64) < g + 1) lo = m + 1; else hi = m; }
    int end = lo;

    int feat = threadIdx.x & 63;
    int rl   = threadIdx.x >> 6;
    float s = 0.f;
    for (int r = start + rl; r < end; r += 4)
        s += g_h[(long long)r * FEAT + feat];

    __shared__ float sm[4][64];
    sm[rl][feat] = s;
    __syncthreads();
    if (rl == 0) {
        float tot = sm[0][feat] + sm[1][feat] + sm[2][feat] + sm[3][feat];
        g_pooled[g * FEAT + feat] = tot / fmaxf((float)(end - start), 1.0f);
    }
}

// ---------------- heads ----------------
__global__ void head_kernel(const float* __restrict__ Wh, const float* __restrict__ bh,
                            const float* __restrict__ Wc, const float* __restrict__ bc,
                            const float* __restrict__ Wo, const float* __restrict__ bo,
                            float* __restrict__ out) {
    __shared__ float sp[64 * 64];
    __shared__ float sh[64 * 64];
    int tid = threadIdx.x;

    for (int i = tid; i < 4096; i += 256) sp[i] = g_pooled[i];
    __syncthreads();

    for (int i = tid; i < 4096; i += 256) {
        int g = i >> 6, j = i & 63;
        float ah = bh[j], ac = bc[j];
        #pragma unroll 8
        for (int k = 0; k < 64; k++) {
            float p = sp[g * 64 + k];
            ah += p * Wh[k * 64 + j];
            ac += p * Wc[k * 64 + j];
        }
        sh[i] = ah;
        out[2048 + i] = ah;
        out[2048 + 4096 + i] = ac;
    }
    __syncthreads();

    int warp = tid >> 5, lane = tid & 31;
    for (int g = warp; g < 64; g += 8) {
        float z = bo[lane];
        #pragma unroll 8
        for (int k = 0; k < 64; k++)
            z += sh[g * 64 + k] * Wo[k * 32 + lane];
        float m = z;
        #pragma unroll
        for (int off = 16; off > 0; off >>= 1)
            m = fmaxf(m, __shfl_xor_sync(0xffffffffu, m, off));
        float s = expf(z - m);
        #pragma unroll
        for (int off = 16; off > 0; off >>= 1)
            s += __shfl_xor_sync(0xffffffffu, s, off);
        out[g * 32 + lane] = z - m - logf(s);
    }
}

// ---------------- launch ----------------
extern "C" void kernel_launch(void* const* d_in, const int* in_sizes, int n_in,
                              void* d_out, int out_size) {
    const float* x     = (const float*)d_in[0];
    const void*  ei    = d_in[1];
    const void*  batch = d_in[2];
    const float* W1    = (const float*)d_in[3];
    const float* root1 = (const float*)d_in[4];
    const float* b1    = (const float*)d_in[5];
    const float* W2    = (const float*)d_in[6];
    const float* root2 = (const float*)d_in[7];
    const float* b2    = (const float*)d_in[8];
    const float* Wh    = (const float*)d_in[9];
    const float* bh    = (const float*)d_in[10];
    const float* Wc    = (const float*)d_in[11];
    const float* bc    = (const float*)d_in[12];
    const float* Wo    = (const float*)d_in[13];
    const float* bo    = (const float*)d_in[14];

    int nN = in_sizes[0] / FEAT;   // 100000
    int nE = in_sizes[1] / 2;      // 1600000

    int eBlocks = (nE + 255) / 256;
    int nBlocks = (nN + 255) / 256;
    int scanBlocks = (nN + 1023) / 1024;
    int gatherBlocks = (nN * 32 + 255) / 256;
    int gemmBlocks = (nN + 63) / 64;

    detect_kernel<<<1, 32>>>(ei, batch, nE, nN);

    // CSR build
    zero_deg_kernel<<<nBlocks, 256>>>(nN);
    hist_kernel<<<eBlocks, 256>>>(ei, nE);
    scan_block_kernel<<<scanBlocks, 256>>>(nN);
    scan_tops_kernel<<<1, 128>>>(scanBlocks);
    scan_add_kernel<<<nBlocks, 256>>>(nN, nE);
    fill_kernel<<<eBlocks, 256>>>(ei, nE);

    // layer 1
    gather_kernel<<<gatherBlocks, 256>>>(x, nN, 0);
    rgcn_gemm<<<gemmBlocks, 256>>>(x, W1, root1, b1, nN, 0);

    // layer 2
    gather_kernel<<<gatherBlocks, 256>>>(x, nN, 1);
    rgcn_gemm<<<gemmBlocks, 256>>>(x, W2, root2, b2, nN, 1);

    // pool + heads
    pool_kernel<<<N_GRAPHS, 256>>>(batch, nN);
    head_kernel<<<1, 256>>>(Wh, bh, Wc, bc, Wo, bo, (float*)d_out);
}

// round 4
// speedup vs baseline: 1.3992x; 1.3992x over previous
#include <cuda_runtime.h>
#include <cuda_bf16.h>

#define MAX_N 100000
#define N_GRAPHS 64
#define FEAT 64
#define MAX_E 1600000

// ---------------- scratch (device globals; no allocations) ----------------
__device__ float g_S[MAX_N * FEAT];       // aggregated (mean) neighbor features
__device__ float g_h[MAX_N * FEAT];       // layer output (reused in-place)
__device__ int   g_deg[MAX_N];            // in-degree histogram
__device__ int   g_rowstart[MAX_N + 1];   // CSR row starts
__device__ int   g_cursor[MAX_N];         // placement cursors
__device__ int   g_srcs[MAX_E];           // CSR: src per edge, bucketed by dst
__device__ int   g_bsum[128];
__device__ int   g_boff[128];
__device__ float g_pooled[N_GRAPHS * FEAT];
__device__ int   g_ei64;
__device__ int   g_b64;

// ---------------- dtype detection (int32 vs int64 indices) ----------------
__global__ void detect_kernel(const void* ei, const void* batch, int nE, int nN) {
    if (threadIdx.x == 0 && blockIdx.x == 0) {
        int e64 = 1;
        const long long* p = (const long long*)ei;
        for (int i = 0; i < 64 && i < nE; i++) {
            long long v = p[i];
            if (v < 0 || v >= (long long)nN) { e64 = 0; break; }
        }
        g_ei64 = e64;
        int b64 = 1;
        const long long* q = (const long long*)batch;
        for (int i = 0; i < 8; i++) {
            int idx = nN / 2 - 1 - i;
            if (idx < 0) break;
            long long v = q[idx];
            if (v < 0 || v >= 64) { b64 = 0; break; }
        }
        g_b64 = b64;
    }
}

// ---------------- CSR build ----------------
__global__ void zero_deg_kernel(int nN) {
    int i = blockIdx.x * blockDim.x + threadIdx.x;
    if (i < nN) g_deg[i] = 0;
}

__global__ void hist_kernel(const void* __restrict__ ei_v, int nE) {
    int e = blockIdx.x * blockDim.x + threadIdx.x;
    if (e >= nE) return;
    int dst;
    if (g_ei64) dst = (int)((const long long*)ei_v)[(long long)nE + e];
    else        dst = ((const int*)ei_v)[nE + e];
    atomicAdd(&g_deg[dst], 1);
}

__global__ void scan_block_kernel(int nN) {
    __shared__ int wsum[8];
    __shared__ int woff[8];
    int blk = blockIdx.x, t = threadIdx.x;
    int base = blk * 1024 + t * 4;
    int v0 = (base + 0 < nN) ? g_deg[base + 0] : 0;
    int v1 = (base + 1 < nN) ? g_deg[base + 1] : 0;
    int v2 = (base + 2 < nN) ? g_deg[base + 2] : 0;
    int v3 = (base + 3 < nN) ? g_deg[base + 3] : 0;
    int i0 = v0, i1 = i0 + v1, i2 = i1 + v2, i3 = i2 + v3;
    int tot = i3;
    int lane = t & 31, w = t >> 5;
    int sc = tot;
    #pragma unroll
    for (int off = 1; off < 32; off <<= 1) {
        int n = __shfl_up_sync(0xffffffffu, sc, off);
        if (lane >= off) sc += n;
    }
    if (lane == 31) wsum[w] = sc;
    __syncthreads();
    if (t < 8) {
        int v = wsum[t];
        int s = v;
        #pragma unroll
        for (int off = 1; off < 8; off <<= 1) {
            int n = __shfl_up_sync(0xffu, s, off);
            if (t >= off) s += n;
        }
        woff[t] = s - v;
        if (t == 7) g_bsum[blk] = s;
    }
    __syncthreads();
    int excl = woff[w] + (sc - tot);
    if (base + 0 < nN) g_rowstart[base + 0] = excl;
    if (base + 1 < nN) g_rowstart[base + 1] = excl + i0;
    if (base + 2 < nN) g_rowstart[base + 2] = excl + i1;
    if (base + 3 < nN) g_rowstart[base + 3] = excl + i2;
}

__global__ void scan_tops_kernel(int nBlocks) {
    __shared__ int wsum[4];
    __shared__ int woff[4];
    int t = threadIdx.x;
    int v = (t < nBlocks) ? g_bsum[t] : 0;
    int lane = t & 31, w = t >> 5;
    int s = v;
    #pragma unroll
    for (int off = 1; off < 32; off <<= 1) {
        int n = __shfl_up_sync(0xffffffffu, s, off);
        if (lane >= off) s += n;
    }
    if (lane == 31) wsum[w] = s;
    __syncthreads();
    if (t < 4) {
        int vv = wsum[t];
        int ss = vv;
        #pragma unroll
        for (int off = 1; off < 4; off <<= 1) {
            int n = __shfl_up_sync(0xfu, ss, off);
            if (t >= off) ss += n;
        }
        woff[t] = ss - vv;
    }
    __syncthreads();
    if (t < nBlocks) g_boff[t] = (s - v) + woff[w];
}

__global__ void scan_add_kernel(int nN, int nE) {
    int i = blockIdx.x * blockDim.x + threadIdx.x;
    if (i < nN) {
        int s = g_rowstart[i] + g_boff[i >> 10];
        g_rowstart[i] = s;
        g_cursor[i] = s;
    }
    if (i == 0) g_rowstart[nN] = nE;
}

__global__ void fill_kernel(const void* __restrict__ ei_v, int nE) {
    int e = blockIdx.x * blockDim.x + threadIdx.x;
    if (e >= nE) return;
    int src, dst;
    if (g_ei64) {
        const long long* ei = (const long long*)ei_v;
        src = (int)ei[e];
        dst = (int)ei[(long long)nE + e];
    } else {
        const int* ei = (const int*)ei_v;
        src = ei[e];
        dst = ei[nE + e];
    }
    int pos = atomicAdd(&g_cursor[dst], 1);
    g_srcs[pos] = src;
}

// ---------------- gather-mean: one warp per node -----------------------
__global__ void gather_kernel(const float* __restrict__ x, int nN, int fromH) {
    int gtid = blockIdx.x * blockDim.x + threadIdx.x;
    int node = gtid >> 5;
    int lane = gtid & 31;
    if (node >= nN) return;
    const float* base = fromH ? (const float*)g_h : x;
    int s = g_rowstart[node];
    int e = g_rowstart[node + 1];
    float ax = 0.f, ay = 0.f;
    int i = s;
    for (; i + 4 <= e; i += 4) {
        int s0 = __ldg(&g_srcs[i]);
        int s1 = __ldg(&g_srcs[i + 1]);
        int s2 = __ldg(&g_srcs[i + 2]);
        int s3 = __ldg(&g_srcs[i + 3]);
        float2 v0 = __ldg((const float2*)(base + (size_t)s0 * FEAT) + lane);
        float2 v1 = __ldg((const float2*)(base + (size_t)s1 * FEAT) + lane);
        float2 v2 = __ldg((const float2*)(base + (size_t)s2 * FEAT) + lane);
        float2 v3 = __ldg((const float2*)(base + (size_t)s3 * FEAT) + lane);
        ax += (v0.x + v1.x) + (v2.x + v3.x);
        ay += (v0.y + v1.y) + (v2.y + v3.y);
    }
    for (; i < e; i++) {
        int s0 = __ldg(&g_srcs[i]);
        float2 v0 = __ldg((const float2*)(base + (size_t)s0 * FEAT) + lane);
        ax += v0.x; ay += v0.y;
    }
    float inv = 1.0f / fmaxf((float)(e - s), 1.0f);
    float2 o = make_float2(ax * inv, ay * inv);
    reinterpret_cast<float2*>(g_S)[node * 32 + lane] = o;
}

// ---------------- fused RGCN layer GEMM with packed f32x2 FMA ------------
// out[i,:] = relu( S[i,:] @ Wrel + X[i,:] @ Wroot + b ), K=128 fused.
// f32x2 lanes = (k, k+1) partial sums. A pairs from row-major input LDS.128;
// B pairs from k-transposed weight tile. Column assignment per thread is
// {tx, tx+16, tx+32, tx+48}: weight-row address (tx+16j)*132 == 4tx (mod 32)
// -> conflict-free LDS.128 across each 8-lane phase.
__global__ void rgcn_gemm(const float* __restrict__ Xin,
                          const float* __restrict__ Wrel,
                          const float* __restrict__ Wroot,
                          const float* __restrict__ bias,
                          int nRows, int xIsH) {
    const float* X = xIsH ? (const float*)g_h : Xin;
    __shared__ float4 sIn[64][33];     // [row][k4], padded
    __shared__ float  sWt[64][132];    // [col][k] transposed weights, padded
    __shared__ float  sB[64];

    int tid = threadIdx.x;
    int rowBase = blockIdx.x * 64;

    // weights: global row-major [k][64] -> smem transposed [col][k]
    #pragma unroll
    for (int i = tid; i < 2048; i += 256) {
        int k = i >> 4, j = i & 15;
        float4 w = (k < 64) ? reinterpret_cast<const float4*>(Wrel)[k * 16 + j]
                            : reinterpret_cast<const float4*>(Wroot)[(k - 64) * 16 + j];
        sWt[4 * j + 0][k] = w.x;
        sWt[4 * j + 1][k] = w.y;
        sWt[4 * j + 2][k] = w.z;
        sWt[4 * j + 3][k] = w.w;
    }
    if (tid < 64) sB[tid] = bias[tid];

    // input tile: K = [S row | X row]
    #pragma unroll
    for (int i = tid; i < 2048; i += 256) {
        int r = i >> 5, q = i & 31;
        int row = rowBase + r;
        float4 v = make_float4(0.f, 0.f, 0.f, 0.f);
        if (row < nRows) {
            if (q < 16) v = reinterpret_cast<const float4*>(g_S)[row * 16 + q];
            else        v = reinterpret_cast<const float4*>(X)[row * 16 + (q - 16)];
        }
        sIn[r][q] = v;
    }
    __syncthreads();

    int tx = tid & 15;   // cols tx + 16*j
    int ty = tid >> 4;   // rows ty + 16*i
    unsigned long long acc[4][4];
    #pragma unroll
    for (int i = 0; i < 4; i++)
        #pragma unroll
        for (int j = 0; j < 4; j++) acc[i][j] = 0ull;

    #pragma unroll 4
    for (int k4 = 0; k4 < 32; ++k4) {
        ulonglong2 a[4];
        #pragma unroll
        for (int i = 0; i < 4; i++)
            a[i] = *reinterpret_cast<const ulonglong2*>(&sIn[ty + 16 * i][k4]);
        ulonglong2 w[4];
        #pragma unroll
        for (int j = 0; j < 4; j++)
            w[j] = *reinterpret_cast<const ulonglong2*>(&sWt[tx + 16 * j][k4 * 4]);
        #pragma unroll
        for (int i = 0; i < 4; i++) {
            #pragma unroll
            for (int j = 0; j < 4; j++) {
                asm("fma.rn.f32x2 %0, %1, %2, %0;"
                    : "+l"(acc[i][j]) : "l"(a[i].x), "l"(w[j].x));
                asm("fma.rn.f32x2 %0, %1, %2, %0;"
                    : "+l"(acc[i][j]) : "l"(a[i].y), "l"(w[j].y));
            }
        }
    }

    #pragma unroll
    for (int i = 0; i < 4; i++) {
        int row = rowBase + ty + 16 * i;
        if (row < nRows) {
            #pragma unroll
            for (int j = 0; j < 4; j++) {
                int col = tx + 16 * j;
                unsigned int lo, hi;
                asm("mov.b64 {%0, %1}, %2;" : "=r"(lo), "=r"(hi) : "l"(acc[i][j]));
                float r = __uint_as_float(lo) + __uint_as_float(hi);
                g_h[row * 64 + col] = fmaxf(r + sB[col], 0.f);
            }
        }
    }
}

// ---------------- global mean pool ----------------
__device__ __forceinline__ long long batch_at(const void* b, int i, int is64) {
    return is64 ? ((const long long*)b)[i] : (long long)((const int*)b)[i];
}

__global__ void pool_kernel(const void* __restrict__ batch, int nRows) {
    int g = blockIdx.x;
    int is64 = g_b64;
    int lo = 0, hi = nRows;
    while (lo < hi) { int m = (lo + hi) >> 1; if (batch_at(batch, m, is64) < g) lo = m + 1; else hi = m; }
    int start = lo;
    lo = 0; hi = nRows;
    while (lo < hi) { int m = (lo + hi) >> 1; if (batch_at(batch, m, is64) < g + 1) lo = m + 1; else hi = m; }
    int end = lo;

    int feat = threadIdx.x & 63;
    int rl   = threadIdx.x >> 6;
    float s = 0.f;
    for (int r = start + rl; r < end; r += 4)
        s += g_h[(long long)r * FEAT + feat];

    __shared__ float sm[4][64];
    sm[rl][feat] = s;
    __syncthreads();
    if (rl == 0) {
        float tot = sm[0][feat] + sm[1][feat] + sm[2][feat] + sm[3][feat];
        g_pooled[g * FEAT + feat] = tot / fmaxf((float)(end - start), 1.0f);
    }
}

// ---------------- heads ----------------
__global__ void head_kernel(const float* __restrict__ Wh, const float* __restrict__ bh,
                            const float* __restrict__ Wc, const float* __restrict__ bc,
                            const float* __restrict__ Wo, const float* __restrict__ bo,
                            float* __restrict__ out) {
    __shared__ float sp[64 * 64];
    __shared__ float sh[64 * 64];
    int tid = threadIdx.x;

    for (int i = tid; i < 4096; i += 256) sp[i] = g_pooled[i];
    __syncthreads();

    for (int i = tid; i < 4096; i += 256) {
        int g = i >> 6, j = i & 63;
        float ah = bh[j], ac = bc[j];
        #pragma unroll 8
        for (int k = 0; k < 64; k++) {
            float p = sp[g * 64 + k];
            ah += p * Wh[k * 64 + j];
            ac += p * Wc[k * 64 + j];
        }
        sh[i] = ah;
        out[2048 + i] = ah;
        out[2048 + 4096 + i] = ac;
    }
    __syncthreads();

    int warp = tid >> 5, lane = tid & 31;
    for (int g = warp; g < 64; g += 8) {
        float z = bo[lane];
        #pragma unroll 8
        for (int k = 0; k < 64; k++)
            z += sh[g * 64 + k] * Wo[k * 32 + lane];
        float m = z;
        #pragma unroll
        for (int off = 16; off > 0; off >>= 1)
            m = fmaxf(m, __shfl_xor_sync(0xffffffffu, m, off));
        float s = expf(z - m);
        #pragma unroll
        for (int off = 16; off > 0; off >>= 1)
            s += __shfl_xor_sync(0xffffffffu, s, off);
        out[g * 32 + lane] = z - m - logf(s);
    }
}

// ---------------- launch ----------------
extern "C" void kernel_launch(void* const* d_in, const int* in_sizes, int n_in,
                              void* d_out, int out_size) {
    const float* x     = (const float*)d_in[0];
    const void*  ei    = d_in[1];
    const void*  batch = d_in[2];
    const float* W1    = (const float*)d_in[3];
    const float* root1 = (const float*)d_in[4];
    const float* b1    = (const float*)d_in[5];
    const float* W2    = (const float*)d_in[6];
    const float* root2 = (const float*)d_in[7];
    const float* b2    = (const float*)d_in[8];
    const float* Wh    = (const float*)d_in[9];
    const float* bh    = (const float*)d_in[10];
    const float* Wc    = (const float*)d_in[11];
    const float* bc    = (const float*)d_in[12];
    const float* Wo    = (const float*)d_in[13];
    const float* bo    = (const float*)d_in[14];

    int nN = in_sizes[0] / FEAT;   // 100000
    int nE = in_sizes[1] / 2;      // 1600000

    int eBlocks = (nE + 255) / 256;
    int nBlocks = (nN + 255) / 256;
    int scanBlocks = (nN + 1023) / 1024;
    int gatherBlocks = (nN * 32 + 255) / 256;
    int gemmBlocks = (nN + 63) / 64;

    detect_kernel<<<1, 32>>>(ei, batch, nE, nN);

    // CSR build
    zero_deg_kernel<<<nBlocks, 256>>>(nN);
    hist_kernel<<<eBlocks, 256>>>(ei, nE);
    scan_block_kernel<<<scanBlocks, 256>>>(nN);
    scan_tops_kernel<<<1, 128>>>(scanBlocks);
    scan_add_kernel<<<nBlocks, 256>>>(nN, nE);
    fill_kernel<<<eBlocks, 256>>>(ei, nE);

    // layer 1
    gather_kernel<<<gatherBlocks, 256>>>(x, nN, 0);
    rgcn_gemm<<<gemmBlocks, 256>>>(x, W1, root1, b1, nN, 0);

    // layer 2
    gather_kernel<<<gatherBlocks, 256>>>(x, nN, 1);
    rgcn_gemm<<<gemmBlocks, 256>>>(x, W2, root2, b2, nN, 1);

    // pool + heads
    pool_kernel<<<N_GRAPHS, 256>>>(batch, nN);
    head_kernel<<<1, 256>>>(Wh, bh, Wc, bc, Wo, bo, (float*)d_out);
}

// round 5
// speedup vs baseline: 1.4440x; 1.0321x over previous
#include <cuda_runtime.h>
#include <cuda_bf16.h>

#define MAX_N 100000
#define N_GRAPHS 64
#define FEAT 64
#define MAX_E 1600000

// ---------------- scratch (device globals; no allocations) ----------------
__device__ float g_S[MAX_N * FEAT];       // aggregated (mean) neighbor features
__device__ float g_h[MAX_N * FEAT];       // layer output (reused in-place)
__device__ int   g_deg[MAX_N];            // in-degree histogram
__device__ int   g_rowstart[MAX_N + 1];   // CSR row starts
__device__ int   g_cursor[MAX_N];         // placement cursors
__device__ int   g_srcs[MAX_E];           // CSR: src per edge, bucketed by dst
__device__ int   g_bsum[128];
__device__ int   g_boff[128];
__device__ float g_pooled[N_GRAPHS * FEAT];
__device__ int   g_ei64;
__device__ int   g_b64;

// ---------------- dtype detection (warp-parallel, one latency) ------------
__global__ void detect_kernel(const void* ei, const void* batch, int nE, int nN) {
    int lane = threadIdx.x;
    // edge_index check: 32 lanes each read one 64-bit word from the dst half
    const long long* p = (const long long*)ei;
    long long v = p[lane];                 // if int32, pairs of random ints
    int ok = (v >= 0 && v < (long long)nN);
    unsigned m = __ballot_sync(0xffffffffu, ok);
    // batch check: probe 64-bit words near end of int32 footprint
    int idx = nN / 2 - 1 - lane;
    long long bv = (idx >= 0) ? ((const long long*)batch)[idx] : 0;
    int bok = (bv >= 0 && bv < 64);
    unsigned bm = __ballot_sync(0xffffffffu, bok);
    if (lane == 0) {
        g_ei64 = (m == 0xffffffffu) ? 1 : 0;
        g_b64  = (bm == 0xffffffffu) ? 1 : 0;
    }
}

// ---------------- CSR build ----------------
__global__ void zero_deg_kernel(int nN) {
    int i = blockIdx.x * blockDim.x + threadIdx.x;
    if (i < nN) g_deg[i] = 0;
}

__global__ void hist_kernel(const void* __restrict__ ei_v, int nE) {
    int e = blockIdx.x * blockDim.x + threadIdx.x;
    if (e >= nE) return;
    int dst;
    if (g_ei64) dst = (int)((const long long*)ei_v)[(long long)nE + e];
    else        dst = ((const int*)ei_v)[nE + e];
    atomicAdd(&g_deg[dst], 1);
}

__global__ void scan_block_kernel(int nN) {
    __shared__ int wsum[8];
    __shared__ int woff[8];
    int blk = blockIdx.x, t = threadIdx.x;
    int base = blk * 1024 + t * 4;
    int v0 = (base + 0 < nN) ? g_deg[base + 0] : 0;
    int v1 = (base + 1 < nN) ? g_deg[base + 1] : 0;
    int v2 = (base + 2 < nN) ? g_deg[base + 2] : 0;
    int v3 = (base + 3 < nN) ? g_deg[base + 3] : 0;
    int i0 = v0, i1 = i0 + v1, i2 = i1 + v2, i3 = i2 + v3;
    int tot = i3;
    int lane = t & 31, w = t >> 5;
    int sc = tot;
    #pragma unroll
    for (int off = 1; off < 32; off <<= 1) {
        int n = __shfl_up_sync(0xffffffffu, sc, off);
        if (lane >= off) sc += n;
    }
    if (lane == 31) wsum[w] = sc;
    __syncthreads();
    if (t < 8) {
        int v = wsum[t];
        int s = v;
        #pragma unroll
        for (int off = 1; off < 8; off <<= 1) {
            int n = __shfl_up_sync(0xffu, s, off);
            if (t >= off) s += n;
        }
        woff[t] = s - v;
        if (t == 7) g_bsum[blk] = s;
    }
    __syncthreads();
    int excl = woff[w] + (sc - tot);
    if (base + 0 < nN) g_rowstart[base + 0] = excl;
    if (base + 1 < nN) g_rowstart[base + 1] = excl + i0;
    if (base + 2 < nN) g_rowstart[base + 2] = excl + i1;
    if (base + 3 < nN) g_rowstart[base + 3] = excl + i2;
}

__global__ void scan_tops_kernel(int nBlocks) {
    __shared__ int wsum[4];
    __shared__ int woff[4];
    int t = threadIdx.x;
    int v = (t < nBlocks) ? g_bsum[t] : 0;
    int lane = t & 31, w = t >> 5;
    int s = v;
    #pragma unroll
    for (int off = 1; off < 32; off <<= 1) {
        int n = __shfl_up_sync(0xffffffffu, s, off);
        if (lane >= off) s += n;
    }
    if (lane == 31) wsum[w] = s;
    __syncthreads();
    if (t < 4) {
        int vv = wsum[t];
        int ss = vv;
        #pragma unroll
        for (int off = 1; off < 4; off <<= 1) {
            int n = __shfl_up_sync(0xfu, ss, off);
            if (t >= off) ss += n;
        }
        woff[t] = ss - vv;
    }
    __syncthreads();
    if (t < nBlocks) g_boff[t] = (s - v) + woff[w];
}

__global__ void scan_add_kernel(int nN, int nE) {
    int i = blockIdx.x * blockDim.x + threadIdx.x;
    if (i < nN) {
        int s = g_rowstart[i] + g_boff[i >> 10];
        g_rowstart[i] = s;
        g_cursor[i] = s;
    }
    if (i == 0) g_rowstart[nN] = nE;
}

__global__ void fill_kernel(const void* __restrict__ ei_v, int nE) {
    int e = blockIdx.x * blockDim.x + threadIdx.x;
    if (e >= nE) return;
    int src, dst;
    if (g_ei64) {
        const long long* ei = (const long long*)ei_v;
        src = (int)ei[e];
        dst = (int)ei[(long long)nE + e];
    } else {
        const int* ei = (const int*)ei_v;
        src = ei[e];
        dst = ei[nE + e];
    }
    int pos = atomicAdd(&g_cursor[dst], 1);
    g_srcs[pos] = src;
}

// ---------------- gather-mean: one warp per node, 2 neighbors per LDG -----
// Lanes 0-15 handle neighbor i (float4 chunks), lanes 16-31 neighbor i+1.
// One LDG.128 warp-instruction covers two 256B neighbor rows; zero divergence
// (both halves share the node's loop bounds). Halves combined via shfl.
__global__ void gather_kernel(const float* __restrict__ x, int nN, int fromH) {
    int gtid = blockIdx.x * blockDim.x + threadIdx.x;
    int node = gtid >> 5;
    int lane = gtid & 31;
    if (node >= nN) return;
    const float* base = fromH ? (const float*)g_h : x;
    int half = lane >> 4;       // 0 or 1
    int c = lane & 15;          // float4 chunk
    int s = g_rowstart[node];
    int e = g_rowstart[node + 1];
    float4 acc = make_float4(0.f, 0.f, 0.f, 0.f);
    int i = s;
    // 4 neighbors per iteration (2 per half), MLP=2 LDG.128 per warp
    for (; i + 4 <= e; i += 4) {
        int a0 = __ldg(&g_srcs[i + half]);
        int a1 = __ldg(&g_srcs[i + 2 + half]);
        float4 v0 = __ldg((const float4*)(base + (size_t)a0 * FEAT) + c);
        float4 v1 = __ldg((const float4*)(base + (size_t)a1 * FEAT) + c);
        acc.x += v0.x + v1.x; acc.y += v0.y + v1.y;
        acc.z += v0.z + v1.z; acc.w += v0.w + v1.w;
    }
    if (i + 2 <= e) {
        int a0 = __ldg(&g_srcs[i + half]);
        float4 v0 = __ldg((const float4*)(base + (size_t)a0 * FEAT) + c);
        acc.x += v0.x; acc.y += v0.y; acc.z += v0.z; acc.w += v0.w;
        i += 2;
    }
    if (i < e) {   // single leftover neighbor: half 0 only
        int a0 = __ldg(&g_srcs[i]);
        float4 v0 = __ldg((const float4*)(base + (size_t)a0 * FEAT) + c);
        if (half == 0) {
            acc.x += v0.x; acc.y += v0.y; acc.z += v0.z; acc.w += v0.w;
        }
    }
    // combine halves: lane c += lane c+16
    acc.x += __shfl_down_sync(0xffffffffu, acc.x, 16);
    acc.y += __shfl_down_sync(0xffffffffu, acc.y, 16);
    acc.z += __shfl_down_sync(0xffffffffu, acc.z, 16);
    acc.w += __shfl_down_sync(0xffffffffu, acc.w, 16);
    if (half == 0) {
        float inv = 1.0f / fmaxf((float)(e - s), 1.0f);
        float4 o = make_float4(acc.x * inv, acc.y * inv, acc.z * inv, acc.w * inv);
        reinterpret_cast<float4*>(g_S)[node * 16 + c] = o;
    }
}

// ---------------- fused RGCN layer GEMM (round-2 scalar, 65.5us) ----------
__global__ void rgcn_gemm(const float* __restrict__ Xin,
                          const float* __restrict__ Wrel,
                          const float* __restrict__ Wroot,
                          const float* __restrict__ bias,
                          int nRows, int xIsH) {
    const float* X = xIsH ? (const float*)g_h : Xin;
    __shared__ float4 sW[128][16];
    __shared__ float4 sIn[64][33];
    __shared__ float  sB[64];

    int tid = threadIdx.x;
    int rowBase = blockIdx.x * 64;

    #pragma unroll
    for (int i = tid; i < 2048; i += 256) {
        int k = i >> 4, j = i & 15;
        sW[k][j] = (k < 64) ? reinterpret_cast<const float4*>(Wrel)[k * 16 + j]
                            : reinterpret_cast<const float4*>(Wroot)[(k - 64) * 16 + j];
    }
    if (tid < 64) sB[tid] = bias[tid];

    #pragma unroll
    for (int i = tid; i < 2048; i += 256) {
        int r = i >> 5, q = i & 31;
        int row = rowBase + r;
        float4 v = make_float4(0.f, 0.f, 0.f, 0.f);
        if (row < nRows) {
            if (q < 16) v = reinterpret_cast<const float4*>(g_S)[row * 16 + q];
            else        v = reinterpret_cast<const float4*>(X)[row * 16 + (q - 16)];
        }
        sIn[r][q] = v;
    }
    __syncthreads();

    int tx = tid & 15;
    int ty = tid >> 4;
    float acc[4][4];
    #pragma unroll
    for (int i = 0; i < 4; i++)
        #pragma unroll
        for (int j = 0; j < 4; j++) acc[i][j] = 0.f;

    #pragma unroll 8
    for (int k4 = 0; k4 < 32; ++k4) {
        float4 a0 = sIn[ty      ][k4];
        float4 a1 = sIn[ty + 16][k4];
        float4 a2 = sIn[ty + 32][k4];
        float4 a3 = sIn[ty + 48][k4];
        float4 w0 = sW[4 * k4 + 0][tx];
        float4 w1 = sW[4 * k4 + 1][tx];
        float4 w2 = sW[4 * k4 + 2][tx];
        float4 w3 = sW[4 * k4 + 3][tx];
        float4 a[4] = {a0, a1, a2, a3};
        #pragma unroll
        for (int i = 0; i < 4; i++) {
            acc[i][0] += a[i].x * w0.x + a[i].y * w1.x + a[i].z * w2.x + a[i].w * w3.x;
            acc[i][1] += a[i].x * w0.y + a[i].y * w1.y + a[i].z * w2.y + a[i].w * w3.y;
            acc[i][2] += a[i].x * w0.z + a[i].y * w1.z + a[i].z * w2.z + a[i].w * w3.z;
            acc[i][3] += a[i].x * w0.w + a[i].y * w1.w + a[i].z * w2.w + a[i].w * w3.w;
        }
    }

    #pragma unroll
    for (int i = 0; i < 4; i++) {
        int row = rowBase + ty + 16 * i;
        if (row < nRows) {
            float4 o;
            o.x = fmaxf(acc[i][0] + sB[tx * 4 + 0], 0.f);
            o.y = fmaxf(acc[i][1] + sB[tx * 4 + 1], 0.f);
            o.z = fmaxf(acc[i][2] + sB[tx * 4 + 2], 0.f);
            o.w = fmaxf(acc[i][3] + sB[tx * 4 + 3], 0.f);
            reinterpret_cast<float4*>(g_h)[row * 16 + tx] = o;
        }
    }
}

// ---------------- global mean pool ----------------
__device__ __forceinline__ long long batch_at(const void* b, int i, int is64) {
    return is64 ? ((const long long*)b)[i] : (long long)((const int*)b)[i];
}

__global__ void pool_kernel(const void* __restrict__ batch, int nRows) {
    int g = blockIdx.x;
    int is64 = g_b64;
    int lo = 0, hi = nRows;
    while (lo < hi) { int m = (lo + hi) >> 1; if (batch_at(batch, m, is64) < g) lo = m + 1; else hi = m; }
    int start = lo;
    lo = 0; hi = nRows;
    while (lo < hi) { int m = (lo + hi) >> 1; if (batch_at(batch, m, is64) < g + 1) lo = m + 1; else hi = m; }
    int end = lo;

    int feat = threadIdx.x & 63;
    int rl   = threadIdx.x >> 6;
    float s = 0.f;
    for (int r = start + rl; r < end; r += 4)
        s += g_h[(long long)r * FEAT + feat];

    __shared__ float sm[4][64];
    sm[rl][feat] = s;
    __syncthreads();
    if (rl == 0) {
        float tot = sm[0][feat] + sm[1][feat] + sm[2][feat] + sm[3][feat];
        g_pooled[g * FEAT + feat] = tot / fmaxf((float)(end - start), 1.0f);
    }
}

// ---------------- heads ----------------
__global__ void head_kernel(const float* __restrict__ Wh, const float* __restrict__ bh,
                            const float* __restrict__ Wc, const float* __restrict__ bc,
                            const float* __restrict__ Wo, const float* __restrict__ bo,
                            float* __restrict__ out) {
    __shared__ float sp[64 * 64];
    __shared__ float sh[64 * 64];
    int tid = threadIdx.x;

    for (int i = tid; i < 4096; i += 256) sp[i] = g_pooled[i];
    __syncthreads();

    for (int i = tid; i < 4096; i += 256) {
        int g = i >> 6, j = i & 63;
        float ah = bh[j], ac = bc[j];
        #pragma unroll 8
        for (int k = 0; k < 64; k++) {
            float p = sp[g * 64 + k];
            ah += p * Wh[k * 64 + j];
            ac += p * Wc[k * 64 + j];
        }
        sh[i] = ah;
        out[2048 + i] = ah;
        out[2048 + 4096 + i] = ac;
    }
    __syncthreads();

    int warp = tid >> 5, lane = tid & 31;
    for (int g = warp; g < 64; g += 8) {
        float z = bo[lane];
        #pragma unroll 8
        for (int k = 0; k < 64; k++)
            z += sh[g * 64 + k] * Wo[k * 32 + lane];
        float m = z;
        #pragma unroll
        for (int off = 16; off > 0; off >>= 1)
            m = fmaxf(m, __shfl_xor_sync(0xffffffffu, m, off));
        float s = expf(z - m);
        #pragma unroll
        for (int off = 16; off > 0; off >>= 1)
            s += __shfl_xor_sync(0xffffffffu, s, off);
        out[g * 32 + lane] = z - m - logf(s);
    }
}

// ---------------- launch ----------------
extern "C" void kernel_launch(void* const* d_in, const int* in_sizes, int n_in,
                              void* d_out, int out_size) {
    const float* x     = (const float*)d_in[0];
    const void*  ei    = d_in[1];
    const void*  batch = d_in[2];
    const float* W1    = (const float*)d_in[3];
    const float* root1 = (const float*)d_in[4];
    const float* b1    = (const float*)d_in[5];
    const float* W2    = (const float*)d_in[6];
    const float* root2 = (const float*)d_in[7];
    const float* b2    = (const float*)d_in[8];
    const float* Wh    = (const float*)d_in[9];
    const float* bh    = (const float*)d_in[10];
    const float* Wc    = (const float*)d_in[11];
    const float* bc    = (const float*)d_in[12];
    const float* Wo    = (const float*)d_in[13];
    const float* bo    = (const float*)d_in[14];

    int nN = in_sizes[0] / FEAT;   // 100000
    int nE = in_sizes[1] / 2;      // 1600000

    int eBlocks = (nE + 255) / 256;
    int nBlocks = (nN + 255) / 256;
    int scanBlocks = (nN + 1023) / 1024;
    int gatherBlocks = (nN * 32 + 255) / 256;
    int gemmBlocks = (nN + 63) / 64;

    detect_kernel<<<1, 32>>>(ei, batch, nE, nN);

    // CSR build
    zero_deg_kernel<<<nBlocks, 256>>>(nN);
    hist_kernel<<<eBlocks, 256>>>(ei, nE);
    scan_block_kernel<<<scanBlocks, 256>>>(nN);
    scan_tops_kernel<<<1, 128>>>(scanBlocks);
    scan_add_kernel<<<nBlocks, 256>>>(nN, nE);
    fill_kernel<<<eBlocks, 256>>>(ei, nE);

    // layer 1
    gather_kernel<<<gatherBlocks, 256>>>(x, nN, 0);
    rgcn_gemm<<<gemmBlocks, 256>>>(x, W1, root1, b1, nN, 0);

    // layer 2
    gather_kernel<<<gatherBlocks, 256>>>(x, nN, 1);
    rgcn_gemm<<<gemmBlocks, 256>>>(x, W2, root2, b2, nN, 1);

    // pool + heads
    pool_kernel<<<N_GRAPHS, 256>>>(batch, nN);
    head_kernel<<<1, 256>>>(Wh, bh, Wc, bc, Wo, bo, (float*)d_out);
}